// round 16
// baseline (speedup 1.0000x reference)
#include <cuda_runtime.h>
#include <math.h>

// Problem constants
#define B_ 256
#define T_ 128
#define D_ 256
#define U_ 512
#define G5 2560   // 5*U
#define G4 2048   // 4*U
#define G3 1536   // 3*U

#define NBLK 128
#define NTHR 256          // 8 warps, 2 K-split sets
#define KT2 64            // staged B chunk (k)
#define AST 544           // full-A smem row stride (floats); 544%32==0
#define ASEG 68           // per-64k segment stride; 68*4B=272 (16B aligned)
#define BSL 32            // B smem stride per (kk,gate): exactly 128B
#define ABUF (32 * AST)           // 17408 floats (full A, staged once/phase)
#define BBUF (KT2 * 4 * BSL)      // 8192 floats per B buffer
#define SMEM_BYTES ((ABUF + 2 * BBUF) * 4)   // 135168

// Scratch (device globals: allocation-free per harness rules)
__device__ float g_xg[(long)B_ * T_ * G5];
__device__ float g_h [B_ * U_];
__device__ float g_h1a[B_ * U_];
__device__ float g_h1b[B_ * U_];
__device__ unsigned g_bar_grp[8 * 32];   // per-m-group counters, 128B apart

__device__ __forceinline__ float hsig(float x) {
    return fminf(fmaxf(0.2f * x + 0.5f, 0.0f), 1.0f);
}

typedef unsigned long long ull;
__device__ __forceinline__ ull pk(float x) {
    ull r; asm("mov.b64 %0, {%1, %1};" : "=l"(r) : "f"(x)); return r;
}
__device__ __forceinline__ ull f2(ull a, ull b, ull c) {
    ull d; asm("fma.rn.f32x2 %0, %1, %2, %3;" : "=l"(d) : "l"(a), "l"(b), "l"(c));
    return d;
}
__device__ __forceinline__ ull a2(ull a, ull b) {
    ull d; asm("add.rn.f32x2 %0, %1, %2;" : "=l"(d) : "l"(a), "l"(b));
    return d;
}
__device__ __forceinline__ float2 up(ull v) {
    float2 r; asm("mov.b64 {%0, %1}, %2;" : "=f"(r.x), "=f"(r.y) : "l"(v));
    return r;
}
__device__ __forceinline__ void pf(const void* p) {
    asm volatile("prefetch.global.L2 [%0];" :: "l"(p));
}

// ---------------------------------------------------------------------------
__global__ void init_h_kernel(const float* __restrict__ h0) {
    int i = blockIdx.x * blockDim.x + threadIdx.x;
    if (i < B_ * U_) g_h[i] = h0[i];
    if (i < 8 * 32) g_bar_grp[i] = 0;
}

// ---------------------------------------------------------------------------
// xg = x @ kernel + bias[0].  (known-good R8 version)
// ---------------------------------------------------------------------------
#define XASL 132
__global__ void __launch_bounds__(256)
xg_gemm_kernel(const float* __restrict__ X,
               const float* __restrict__ W,
               const float* __restrict__ bias) {
    __shared__ float As[8 * XASL];
    __shared__ float Bs[8 * 128];
    const int bm = blockIdx.y * 128;
    const int bn = blockIdx.x * 128;
    const int tid  = threadIdx.x;
    const int lane = tid & 31;
    const int wrp  = tid >> 5;
    const int mG = lane & 3, nG = lane >> 2;
    const int mW = wrp & 3,  nW = wrp >> 2;
    const int mOff = mW * 32 + mG * 8;
    const int nOff = nW * 64 + nG * 8;
    const int arow = tid >> 1, acol = (tid & 1) * 4;
    const int brow = tid >> 5, bcol = (tid & 31) * 4;

    ull acc[8][4];
#pragma unroll
    for (int i = 0; i < 8; i++)
#pragma unroll
        for (int j = 0; j < 4; j++) acc[i][j] = 0ull;

    const float* Xp = X + (bm + arow) * D_ + acol;
    const float* Wp = W + brow * G5 + bn + bcol;

    for (int k0 = 0; k0 < D_; k0 += 8) {
        float4 av = *(const float4*)(Xp + k0);
        As[(acol + 0) * XASL + arow] = av.x;
        As[(acol + 1) * XASL + arow] = av.y;
        As[(acol + 2) * XASL + arow] = av.z;
        As[(acol + 3) * XASL + arow] = av.w;
        *(float4*)&Bs[brow * 128 + bcol] = *(const float4*)(Wp + (long)k0 * G5);
        __syncthreads();
#pragma unroll
        for (int k = 0; k < 8; k++) {
            float4 a0 = *(const float4*)(As + k * XASL + mOff);
            float4 a1 = *(const float4*)(As + k * XASL + mOff + 4);
            ull a[8] = {pk(a0.x), pk(a0.y), pk(a0.z), pk(a0.w),
                        pk(a1.x), pk(a1.y), pk(a1.z), pk(a1.w)};
            const ulonglong2* bp = (const ulonglong2*)(Bs + k * 128 + nOff);
            ulonglong2 b01 = bp[0], b23 = bp[1];
            ull b[4] = {b01.x, b01.y, b23.x, b23.y};
#pragma unroll
            for (int i = 0; i < 8; i++)
#pragma unroll
                for (int j = 0; j < 4; j++) acc[i][j] = f2(a[i], b[j], acc[i][j]);
        }
        __syncthreads();
    }

#pragma unroll
    for (int i = 0; i < 8; i++) {
        int m = bm + mOff + i;
        float* o = g_xg + (long)m * G5 + bn + nOff;
#pragma unroll
        for (int j = 0; j < 4; j++) {
            float2 v = up(acc[i][j]);
            o[2 * j]     = v.x + bias[bn + nOff + 2 * j];
            o[2 * j + 1] = v.y + bias[bn + nOff + 2 * j + 1];
        }
    }
}

// ---------------------------------------------------------------------------
// Per-m-group barrier (16 blocks): release-arrive + acquire-spin.
// ---------------------------------------------------------------------------
__device__ __forceinline__ void grp_bar(unsigned* ctr, unsigned target) {
    __syncthreads();
    if (threadIdx.x == 0) {
        asm volatile("red.release.gpu.global.add.u32 [%0], %1;"
                     :: "l"(ctr), "r"(1u) : "memory");
        unsigned v;
        do {
            asm volatile("ld.acquire.gpu.global.u32 %0, [%1];"
                         : "=r"(v) : "l"(ctr) : "memory");
        } while (v < target);
    }
    __syncthreads();
}

// ---------------------------------------------------------------------------
// Pre-stage W chunk 0 of the NEXT phase into Bs buf0 (local smem only).
// ---------------------------------------------------------------------------
template <int G>
__device__ __forceinline__ void preW(const float* __restrict__ W, int ldw,
                                     int u0, float* Bs0) {
    const int tid = threadIdx.x;
    float4 v[2 * G]; int so[2 * G];
#pragma unroll
    for (int r = 0; r < 2 * G; r++) {
        int fi  = tid + r * NTHR;
        int kk  = fi / (8 * G);
        int rem = fi - kk * 8 * G;
        int g   = rem >> 3;
        int u4  = (rem & 7) * 4;
        so[r] = (kk * G + g) * BSL + u4;
        v[r]  = __ldg((const float4*)(W + (long)kk * ldw + g * U_ + u0 + u4));
    }
#pragma unroll
    for (int r = 0; r < 2 * G; r++) *(float4*)(Bs0 + so[r]) = v[r];
}

// ---------------------------------------------------------------------------
// Stage full A (32 rows x 512 k) once per phase:
//   word addr = m*AST + (k>>6)*ASEG + (k&63)
// Thread: m = tid>>3, kseg = tid&7 handles k = kseg*64 .. +63.
// 16B-aligned float4 stores (ASEG=68, AST=544, both %4==0); each
// quarter-wavefront (one m, 8 ksegs) spans all 32 banks -> conflict-free.
// ---------------------------------------------------------------------------
__device__ __forceinline__ void stage_A(float* As,
                                        const float* __restrict__ Asrc,
                                        int m0) {
    const int tid  = threadIdx.x;
    const int m    = tid >> 3;
    const int kseg = tid & 7;
    const float* src = Asrc + (m0 + m) * U_ + kseg * 64;
    float* dst = As + m * AST + kseg * ASEG;
#pragma unroll
    for (int j4 = 0; j4 < 16; j4++) {
        float4 v = __ldcg((const float4*)(src + j4 * 4));
        *(float4*)(dst + j4 * 4) = v;
    }
}

// ---------------------------------------------------------------------------
// B-double-buffered K-split tile GEMM; A pre-staged for whole phase.
// 8 warps = 2 K-sets x 4 warps; block tile 32m x (G x 32u).
// A read per kk: scalar broadcast, rows aOff/aOff+1, col c*ASEG + S*32 + kk2.
// ---------------------------------------------------------------------------
template <int G>
__device__ __forceinline__ void mm_tile_db(const float* As, float* Bs,
                                           const float* __restrict__ W, int ldw,
                                           int u0, ull* acc) {
    const int tid  = threadIdx.x;
    const int lane = tid & 31;
    const int wrp  = tid >> 5;
    const int S    = wrp >> 2;
    const int w4   = wrp & 3;
    const int mG = lane & 3, uG = lane >> 2;
    const int aOff = w4 * 8 + mG * 2;

#pragma unroll
    for (int i = 0; i < 4 * G; i++) acc[i] = 0ull;

    int bso[2 * G];
    int bgo[2 * G];
#pragma unroll
    for (int r = 0; r < 2 * G; r++) {
        int fi  = tid + r * NTHR;
        int kk  = fi / (8 * G);
        int rem = fi - kk * 8 * G;
        int g   = rem >> 3;
        int u4  = (rem & 7) * 4;
        bso[r] = (kk * G + g) * BSL + u4;
        bgo[r] = kk * ldw + g * U_ + u0 + u4;
    }

    // chunk1 W loads (chunk0 already in buf0 via preW)
    float4 pb[2 * G];
#pragma unroll
    for (int r = 0; r < 2 * G; r++)
        pb[r] = __ldg((const float4*)(W + (long)KT2 * ldw + bgo[r]));

    __syncthreads();     // A staged (stage_A) + buf0 ready

#pragma unroll
    for (int c = 0; c < 8; c++) {
        if (c < 7) {
            float* Bsn = Bs + ((c + 1) & 1) * BBUF;
#pragma unroll
            for (int r = 0; r < 2 * G; r++)
                *(float4*)(Bsn + bso[r]) = pb[r];
            if (c < 6) {
#pragma unroll
                for (int r = 0; r < 2 * G; r++)
                    pb[r] = __ldg((const float4*)(W + (long)(c + 2) * KT2 * ldw
                                                  + bgo[r]));
            }
        }
        const float* Bsb = Bs + (c & 1) * BBUF;
        const float* A0p = As + (aOff + 0) * AST + c * ASEG + S * 32;
        const float* A1p = A0p + AST;
        const float* Bbase = Bsb + (S * 32) * G * BSL + uG * 4;
#pragma unroll 8
        for (int kk2 = 0; kk2 < 32; kk2++) {
            ull A0 = pk(A0p[kk2]);
            ull A1 = pk(A1p[kk2]);
            const float* Bk = Bbase + kk2 * G * BSL;
#pragma unroll
            for (int g = 0; g < G; g++) {
                ulonglong2 bb = *(const ulonglong2*)(Bk + g * BSL);
                acc[g * 4 + 0] = f2(A0, bb.x, acc[g * 4 + 0]);
                acc[g * 4 + 1] = f2(A0, bb.y, acc[g * 4 + 1]);
                acc[g * 4 + 2] = f2(A1, bb.x, acc[g * 4 + 2]);
                acc[g * 4 + 3] = f2(A1, bb.y, acc[g * 4 + 3]);
            }
        }
        if (c < 7) __syncthreads();
    }
}

// ---------------------------------------------------------------------------
// Cross-set reduction: set 1 dumps partials into Red (= Bs buf1),
// set 0 accumulates. Valid full acc in tid < 128 afterwards.
// ---------------------------------------------------------------------------
template <int G>
__device__ __forceinline__ void k_reduce(ull* Red, ull* acc) {
    const int tid = threadIdx.x;
    __syncthreads();
    if (tid >= 128) {
#pragma unroll
        for (int j = 0; j < 4 * G; j++) Red[(tid - 128) * 17 + j] = acc[j];
    }
    __syncthreads();
    if (tid < 128) {
#pragma unroll
        for (int j = 0; j < 4 * G; j++) acc[j] = a2(acc[j], Red[tid * 17 + j]);
    }
}

// ---------------------------------------------------------------------------
// Persistent scan kernel: 128 blocks x 256 threads, per-m-group barriers.
// ---------------------------------------------------------------------------
__global__ void __launch_bounds__(NTHR)
scan_kernel(const float* __restrict__ Wr, const float* __restrict__ Wt,
            const float* __restrict__ bias, const float* __restrict__ tbias,
            float* __restrict__ out) {
    extern __shared__ __align__(16) float smem[];
    float* As = smem;                   // ABUF (full A, segmented layout)
    float* Bs = smem + ABUF;            // 2 x BBUF
    ull*  Red = (ull*)(Bs + BBUF);      // overlays buf1

    const int u0   = (blockIdx.x & 15) * 32;
    const int grp  = blockIdx.x >> 4;
    const int m0   = grp * 32;
    unsigned* ctr  = &g_bar_grp[grp * 32];
    const int tid  = threadIdx.x;
    const int lane = tid & 31;
    const int wrp  = tid >> 5;
    const int mG = lane & 3;
    const int mBase = m0 + (wrp & 3) * 8 + mG * 2;
    const int uBase = u0 + (lane >> 2) * 4;

    const float* Wt1 = Wt + (long)U_ * G3;

    unsigned barno = 0;
    ull acc[16];
    float h1r[2][2][2];   // [i][p][h2]  (valid in tid<128)
    float hlr[2][2][2];

    preW<4>(Wr, G4, u0, Bs);            // W chunk0 for the first REC

    for (int t = 0; t < T_; t++) {
        // L2-prefetch this step's xg epilogue lines
        if (tid < 128) {
#pragma unroll
            for (int i = 0; i < 2; i++) {
                const float* xq = g_xg + ((long)(mBase + i) * T_ + t) * G5 + uBase;
                pf(xq); pf(xq + U_); pf(xq + 2 * U_); pf(xq + 3 * U_); pf(xq + 4 * U_);
            }
        }

        // ---- phase REC: hg = h @ Wr (4 gates: z, r, hr, l) ----
        stage_A(As, g_h, m0);
        mm_tile_db<4>(As, Bs, Wr, G4, u0, acc);
        k_reduce<4>(Red, acc);
        if (tid < 128) {
#pragma unroll
            for (int i = 0; i < 2; i++) {
                const int b = mBase + i;
                const float* xp = g_xg + ((long)b * T_ + t) * G5;
#pragma unroll
                for (int p = 0; p < 2; p++) {
                    float2 vz = up(acc[0  + i * 2 + p]);
                    float2 vr = up(acc[4  + i * 2 + p]);
                    float2 vh = up(acc[8  + i * 2 + p]);
                    float2 vl = up(acc[12 + i * 2 + p]);
#pragma unroll
                    for (int h2 = 0; h2 < 2; h2++) {
                        const int u = uBase + p * 2 + h2;
                        float az = h2 ? vz.y : vz.x;
                        float ar = h2 ? vr.y : vr.x;
                        float ah = h2 ? vh.y : vh.x;
                        float al = h2 ? vl.y : vl.x;
                        float z  = hsig(__ldg(xp + u) + az + __ldg(bias + G5 + u));
                        float r  = hsig(__ldg(xp + U_ + u) + ar +
                                        __ldg(bias + G5 + U_ + u));
                        float hh = tanhf(__ldg(xp + 2 * U_ + u) +
                                         r * (ah + __ldg(bias + G5 + 2 * U_ + u)));
                        float hold = __ldcg(g_h + (long)b * U_ + u);
                        float h1 = z * hold + (1.0f - z) * hh;
                        __stcg(g_h1a + (long)b * U_ + u, h1);
                        h1r[i][p][h2] = h1;
                        hlr[i][p][h2] = al + __ldg(bias + G5 + 3 * U_ + u);
                    }
                }
            }
        }
        preW<3>(Wt, G3, u0, Bs);
        grp_bar(ctr, ++barno * 16);

        // ---- phase T0 ----
        stage_A(As, g_h1a, m0);
        mm_tile_db<3>(As, Bs, Wt, G3, u0, acc);
        k_reduce<3>(Red, acc);
        if (tid < 128) {
#pragma unroll
            for (int i = 0; i < 2; i++) {
                const int b = mBase + i;
#pragma unroll
                for (int p = 0; p < 2; p++) {
                    float2 vz = up(acc[0 + i * 2 + p]);
                    float2 vr = up(acc[4 + i * 2 + p]);
                    float2 vh = up(acc[8 + i * 2 + p]);
#pragma unroll
                    for (int h2 = 0; h2 < 2; h2++) {
                        const int u = uBase + p * 2 + h2;
                        float az = h2 ? vz.y : vz.x;
                        float ar = h2 ? vr.y : vr.x;
                        float ah = h2 ? vh.y : vh.x;
                        float zt = hsig(az + __ldg(tbias + u));
                        float rt = hsig(ar + __ldg(tbias + U_ + u));
                        float ht = tanhf(rt * (ah + __ldg(tbias + 2 * U_ + u)));
                        float h1 = zt * h1r[i][p][h2] + (1.0f - zt) * ht;
                        __stcg(g_h1b + (long)b * U_ + u, h1);
                        h1r[i][p][h2] = h1;
                    }
                }
            }
        }
        preW<3>(Wt1, G3, u0, Bs);
        grp_bar(ctr, ++barno * 16);

        // ---- phase T1 + final combine ----
        stage_A(As, g_h1b, m0);
        mm_tile_db<3>(As, Bs, Wt1, G3, u0, acc);
        k_reduce<3>(Red, acc);
        if (tid < 128) {
#pragma unroll
            for (int i = 0; i < 2; i++) {
                const int b = mBase + i;
                const float* xp = g_xg + ((long)b * T_ + t) * G5;
#pragma unroll
                for (int p = 0; p < 2; p++) {
                    float2 vz = up(acc[0 + i * 2 + p]);
                    float2 vr = up(acc[4 + i * 2 + p]);
                    float2 vh = up(acc[8 + i * 2 + p]);
#pragma unroll
                    for (int h2 = 0; h2 < 2; h2++) {
                        const int u = uBase + p * 2 + h2;
                        float az = h2 ? vz.y : vz.x;
                        float ar = h2 ? vr.y : vr.x;
                        float ah = h2 ? vh.y : vh.x;
                        float zt = hsig(az + __ldg(tbias + G3 + u));
                        float rt = hsig(ar + __ldg(tbias + G3 + U_ + u));
                        float ht = tanhf(rt * (ah + __ldg(tbias + G3 + 2 * U_ + u)));
                        float h1 = zt * h1r[i][p][h2] + (1.0f - zt) * ht;
                        float l  = hsig(__ldg(xp + 3 * U_ + u) + hlr[i][p][h2]);
                        float ho = l * h1 +
                                   (1.0f - l) * tanhf(__ldg(xp + 4 * U_ + u));
                        __stcg(g_h + (long)b * U_ + u, ho);
                        out[((long)b * T_ + t) * U_ + u] = ho;
                    }
                }
            }
        }
        preW<4>(Wr, G4, u0, Bs);
        grp_bar(ctr, ++barno * 16);
    }
}

// ---------------------------------------------------------------------------
extern "C" void kernel_launch(void* const* d_in, const int* in_sizes, int n_in,
                              void* d_out, int out_size) {
    (void)in_sizes; (void)n_in; (void)out_size;
    const float* x      = (const float*)d_in[0];
    const float* h0     = (const float*)d_in[1];
    const float* kernel = (const float*)d_in[2];
    const float* Wr     = (const float*)d_in[3];
    const float* Wt     = (const float*)d_in[4];
    const float* bias   = (const float*)d_in[5];
    const float* tbias  = (const float*)d_in[6];
    float* out = (float*)d_out;

    static int smem_set = 0;
    if (!smem_set) {
        cudaFuncSetAttribute(scan_kernel,
                             cudaFuncAttributeMaxDynamicSharedMemorySize,
                             SMEM_BYTES);
        smem_set = 1;
    }

    init_h_kernel<<<(B_ * U_ + 255) / 256, 256>>>(h0);
    xg_gemm_kernel<<<dim3(G5 / 128, (B_ * T_) / 128), 256>>>(x, kernel, bias);
    scan_kernel<<<NBLK, NTHR, SMEM_BYTES>>>(Wr, Wt, bias, tbias, out);
}

// round 17
// speedup vs baseline: 1.2142x; 1.2142x over previous
#include <cuda_runtime.h>
#include <math.h>

// Problem constants
#define B_ 256
#define T_ 128
#define D_ 256
#define U_ 512
#define G5 2560   // 5*U
#define G4 2048   // 4*U
#define G3 1536   // 3*U

#define NBLK 128
#define NTHR 256          // 8 warps, 2 K-split sets
#define KCH 128           // staged K chunk (4 chunks per phase)
#define ASL2 132          // A smem row stride ([m][k], floats)
#define BSL 32            // B smem stride per (kk,gate): exactly 128B
#define ABUF (32 * ASL2)          // 4224 floats per A buffer
#define BBUF (KCH * 4 * BSL)      // 16384 floats per B buffer
#define SMEM_BYTES ((2 * ABUF + 2 * BBUF) * 4)   // 164864

// Scratch (device globals: allocation-free per harness rules)
__device__ float g_xg[(long)B_ * T_ * G5];
__device__ float g_h [B_ * U_];
__device__ float g_h1a[B_ * U_];
__device__ float g_h1b[B_ * U_];
__device__ unsigned g_bar_ctr;

__device__ __forceinline__ float hsig(float x) {
    return fminf(fmaxf(0.2f * x + 0.5f, 0.0f), 1.0f);
}

typedef unsigned long long ull;
__device__ __forceinline__ ull pk(float x) {
    ull r; asm("mov.b64 %0, {%1, %1};" : "=l"(r) : "f"(x)); return r;
}
__device__ __forceinline__ ull f2(ull a, ull b, ull c) {
    ull d; asm("fma.rn.f32x2 %0, %1, %2, %3;" : "=l"(d) : "l"(a), "l"(b), "l"(c));
    return d;
}
__device__ __forceinline__ ull a2(ull a, ull b) {
    ull d; asm("add.rn.f32x2 %0, %1, %2;" : "=l"(d) : "l"(a), "l"(b));
    return d;
}
__device__ __forceinline__ float2 up(ull v) {
    float2 r; asm("mov.b64 {%0, %1}, %2;" : "=f"(r.x), "=f"(r.y) : "l"(v));
    return r;
}
__device__ __forceinline__ void pf(const void* p) {
    asm volatile("prefetch.global.L2 [%0];" :: "l"(p));
}

// ---------------------------------------------------------------------------
__global__ void init_h_kernel(const float* __restrict__ h0) {
    int i = blockIdx.x * blockDim.x + threadIdx.x;
    if (i < B_ * U_) g_h[i] = h0[i];
    if (i == 0) g_bar_ctr = 0;
}

// ---------------------------------------------------------------------------
// xg = x @ kernel + bias[0].  (known-good R8 version)
// ---------------------------------------------------------------------------
#define XASL 132
__global__ void __launch_bounds__(256)
xg_gemm_kernel(const float* __restrict__ X,
               const float* __restrict__ W,
               const float* __restrict__ bias) {
    __shared__ float As[8 * XASL];
    __shared__ float Bs[8 * 128];
    const int bm = blockIdx.y * 128;
    const int bn = blockIdx.x * 128;
    const int tid  = threadIdx.x;
    const int lane = tid & 31;
    const int wrp  = tid >> 5;
    const int mG = lane & 3, nG = lane >> 2;
    const int mW = wrp & 3,  nW = wrp >> 2;
    const int mOff = mW * 32 + mG * 8;
    const int nOff = nW * 64 + nG * 8;
    const int arow = tid >> 1, acol = (tid & 1) * 4;
    const int brow = tid >> 5, bcol = (tid & 31) * 4;

    ull acc[8][4];
#pragma unroll
    for (int i = 0; i < 8; i++)
#pragma unroll
        for (int j = 0; j < 4; j++) acc[i][j] = 0ull;

    const float* Xp = X + (bm + arow) * D_ + acol;
    const float* Wp = W + brow * G5 + bn + bcol;

    for (int k0 = 0; k0 < D_; k0 += 8) {
        float4 av = *(const float4*)(Xp + k0);
        As[(acol + 0) * XASL + arow] = av.x;
        As[(acol + 1) * XASL + arow] = av.y;
        As[(acol + 2) * XASL + arow] = av.z;
        As[(acol + 3) * XASL + arow] = av.w;
        *(float4*)&Bs[brow * 128 + bcol] = *(const float4*)(Wp + (long)k0 * G5);
        __syncthreads();
#pragma unroll
        for (int k = 0; k < 8; k++) {
            float4 a0 = *(const float4*)(As + k * XASL + mOff);
            float4 a1 = *(const float4*)(As + k * XASL + mOff + 4);
            ull a[8] = {pk(a0.x), pk(a0.y), pk(a0.z), pk(a0.w),
                        pk(a1.x), pk(a1.y), pk(a1.z), pk(a1.w)};
            const ulonglong2* bp = (const ulonglong2*)(Bs + k * 128 + nOff);
            ulonglong2 b01 = bp[0], b23 = bp[1];
            ull b[4] = {b01.x, b01.y, b23.x, b23.y};
#pragma unroll
            for (int i = 0; i < 8; i++)
#pragma unroll
                for (int j = 0; j < 4; j++) acc[i][j] = f2(a[i], b[j], acc[i][j]);
        }
        __syncthreads();
    }

#pragma unroll
    for (int i = 0; i < 8; i++) {
        int m = bm + mOff + i;
        float* o = g_xg + (long)m * G5 + bn + nOff;
#pragma unroll
        for (int j = 0; j < 4; j++) {
            float2 v = up(acc[i][j]);
            o[2 * j]     = v.x + bias[bn + nOff + 2 * j];
            o[2 * j + 1] = v.y + bias[bn + nOff + 2 * j + 1];
        }
    }
}

// ---------------------------------------------------------------------------
// Grid-wide barrier: release-arrive + acquire-spin (known-good R9/R14).
// ---------------------------------------------------------------------------
__device__ __forceinline__ void grid_bar(unsigned target) {
    __syncthreads();
    if (threadIdx.x == 0) {
        asm volatile("red.release.gpu.global.add.u32 [%0], %1;"
                     :: "l"(&g_bar_ctr), "r"(1u) : "memory");
        unsigned v;
        do {
            asm volatile("ld.acquire.gpu.global.u32 %0, [%1];"
                         : "=r"(v) : "l"(&g_bar_ctr) : "memory");
        } while (v < target);
    }
    __syncthreads();
}

// ---------------------------------------------------------------------------
// Stage one B K-chunk (KCH x G x 32u) into dstB, bursts of 4 float4.
// Mapping: r = 0..4G-1;  plane = r>>2 (gate), kk = (tid>>3) + 32*(r&3).
// No persistent register arrays; LDGs overlap surrounding compute.
// ---------------------------------------------------------------------------
template <int G>
__device__ __forceinline__ void stageB_chunk(const float* __restrict__ W,
                                             int ldw, int u0, int kbase,
                                             float* dstB) {
    const int tid = threadIdx.x;
    const int kk0 = tid >> 3;
    const int u4  = (tid & 7) * 4;
#pragma unroll
    for (int r0 = 0; r0 < 4 * G; r0 += 4) {
        float4 v[4]; int so[4];
#pragma unroll
        for (int j = 0; j < 4; j++) {
            int r = r0 + j;
            int plane = r >> 2;
            int kkv = kk0 + 32 * (r & 3);
            so[j] = (kkv * G + plane) * BSL + u4;
            v[j] = __ldg((const float4*)(W + (long)(kbase + kkv) * ldw
                                         + plane * U_ + u0 + u4));
        }
#pragma unroll
        for (int j = 0; j < 4; j++) *(float4*)(dstB + so[j]) = v[j];
    }
}

// Stage one A K-chunk (32m x KCH) into dstA. Thread: mA=tid>>3, 16 k's.
__device__ __forceinline__ void stageA_chunk(const float* __restrict__ Arow,
                                             int kbase, float* dstA,
                                             int mA, int kA16) {
    const float* s = Arow + kbase + kA16;
    float4 a0 = __ldcg((const float4*)(s));
    float4 a1 = __ldcg((const float4*)(s + 4));
    float4 a2 = __ldcg((const float4*)(s + 8));
    float4 a3 = __ldcg((const float4*)(s + 12));
    float* d = dstA + mA * ASL2 + kA16;
    *(float4*)(d)      = a0;
    *(float4*)(d + 4)  = a1;
    *(float4*)(d + 8)  = a2;
    *(float4*)(d + 12) = a3;
}

// ---------------------------------------------------------------------------
// Double-buffered K-split tile GEMM, KCH=128 chunks (4/phase, 4 syncs).
// Assumes W chunk0 pre-staged in Bs buf0 (preW before the barrier).
// 8 warps = 2 K-sets x 4 warps; block tile 32m x (G x 32u).
// Set S computes kk = S*64 + [0,64) of each chunk.
// ---------------------------------------------------------------------------
template <int G>
__device__ __forceinline__ void mm_tile_db(float* As, float* Bs,
                                           const float* __restrict__ Asrc,
                                           const float* __restrict__ W, int ldw,
                                           int m0, int u0, ull* acc) {
    const int tid  = threadIdx.x;
    const int lane = tid & 31;
    const int wrp  = tid >> 5;
    const int S    = wrp >> 2;
    const int w4   = wrp & 3;
    const int mG = lane & 3, uG = lane >> 2;
    const int aOff = w4 * 8 + mG * 2;
    const int mA   = tid >> 3;
    const int kA16 = (tid & 7) * 16;

#pragma unroll
    for (int i = 0; i < 4 * G; i++) acc[i] = 0ull;

    const float* Arow = Asrc + (m0 + mA) * U_;

    // stage A chunk0 into buf0 (W chunk0 already there via preW)
    stageA_chunk(Arow, 0, As, mA, kA16);
    __syncthreads();

#pragma unroll
    for (int c = 0; c < 4; c++) {
        if (c < 3) {
            float* Asn = As + ((c + 1) & 1) * ABUF;
            float* Bsn = Bs + ((c + 1) & 1) * BBUF;
            stageA_chunk(Arow, (c + 1) * KCH, Asn, mA, kA16);
            stageB_chunk<G>(W, ldw, u0, (c + 1) * KCH, Bsn);
        }
        const float* Asb = As + (c & 1) * ABUF;
        const float* Bsb = Bs + (c & 1) * BBUF;
        const float* A0p = Asb + (aOff + 0) * ASL2 + S * 64;
        const float* A1p = A0p + ASL2;
        const float* Bbase = Bsb + (S * 64) * G * BSL + uG * 4;
#pragma unroll 8
        for (int kk2 = 0; kk2 < 64; kk2++) {
            ull A0 = pk(A0p[kk2]);
            ull A1 = pk(A1p[kk2]);
            const float* Bk = Bbase + kk2 * G * BSL;
#pragma unroll
            for (int g = 0; g < G; g++) {
                ulonglong2 bb = *(const ulonglong2*)(Bk + g * BSL);
                acc[g * 4 + 0] = f2(A0, bb.x, acc[g * 4 + 0]);
                acc[g * 4 + 1] = f2(A0, bb.y, acc[g * 4 + 1]);
                acc[g * 4 + 2] = f2(A1, bb.x, acc[g * 4 + 2]);
                acc[g * 4 + 3] = f2(A1, bb.y, acc[g * 4 + 3]);
            }
        }
        if (c < 3) __syncthreads();
    }
}

// ---------------------------------------------------------------------------
// Cross-set reduction: set 1 dumps partials into Red (= Bs buf1),
// set 0 accumulates. Valid full acc in tid < 128 afterwards.
// ---------------------------------------------------------------------------
template <int G>
__device__ __forceinline__ void k_reduce(ull* Red, ull* acc) {
    const int tid = threadIdx.x;
    __syncthreads();
    if (tid >= 128) {
#pragma unroll
        for (int j = 0; j < 4 * G; j++) Red[(tid - 128) * 17 + j] = acc[j];
    }
    __syncthreads();
    if (tid < 128) {
#pragma unroll
        for (int j = 0; j < 4 * G; j++) acc[j] = a2(acc[j], Red[tid * 17 + j]);
    }
}

// ---------------------------------------------------------------------------
// Persistent scan kernel: 128 blocks x 256 threads, dynamic smem.
// ---------------------------------------------------------------------------
__global__ void __launch_bounds__(NTHR)
scan_kernel(const float* __restrict__ Wr, const float* __restrict__ Wt,
            const float* __restrict__ bias, const float* __restrict__ tbias,
            float* __restrict__ out) {
    extern __shared__ __align__(16) float smem[];
    float* As = smem;                   // 2 x ABUF
    float* Bs = smem + 2 * ABUF;        // 2 x BBUF
    ull*  Red = (ull*)(Bs + BBUF);      // overlays buf1

    const int u0   = (blockIdx.x & 15) * 32;
    const int m0   = (blockIdx.x >> 4) * 32;
    const int tid  = threadIdx.x;
    const int lane = tid & 31;
    const int wrp  = tid >> 5;
    const int mG = lane & 3;
    const int mBase = m0 + (wrp & 3) * 8 + mG * 2;
    const int uBase = u0 + (lane >> 2) * 4;

    const float* Wt1 = Wt + (long)U_ * G3;

    unsigned barno = 0;
    ull acc[16];
    float h1r[2][2][2];   // [i][p][h2]  (valid in tid<128)
    float hlr[2][2][2];

    stageB_chunk<4>(Wr, G4, u0, 0, Bs);   // W chunk0 for the first REC

    for (int t = 0; t < T_; t++) {
        // L2-prefetch this step's xg epilogue lines
        if (tid < 128) {
#pragma unroll
            for (int i = 0; i < 2; i++) {
                const float* xq = g_xg + ((long)(mBase + i) * T_ + t) * G5 + uBase;
                pf(xq); pf(xq + U_); pf(xq + 2 * U_); pf(xq + 3 * U_); pf(xq + 4 * U_);
            }
        }

        // ---- phase REC: hg = h @ Wr (4 gates: z, r, hr, l) ----
        mm_tile_db<4>(As, Bs, g_h, Wr, G4, m0, u0, acc);
        k_reduce<4>(Red, acc);
        if (tid < 128) {
#pragma unroll
            for (int i = 0; i < 2; i++) {
                const int b = mBase + i;
                const float* xp = g_xg + ((long)b * T_ + t) * G5;
#pragma unroll
                for (int p = 0; p < 2; p++) {
                    float2 vz = up(acc[0  + i * 2 + p]);
                    float2 vr = up(acc[4  + i * 2 + p]);
                    float2 vh = up(acc[8  + i * 2 + p]);
                    float2 vl = up(acc[12 + i * 2 + p]);
#pragma unroll
                    for (int h2 = 0; h2 < 2; h2++) {
                        const int u = uBase + p * 2 + h2;
                        float az = h2 ? vz.y : vz.x;
                        float ar = h2 ? vr.y : vr.x;
                        float ah = h2 ? vh.y : vh.x;
                        float al = h2 ? vl.y : vl.x;
                        float z  = hsig(__ldg(xp + u) + az + __ldg(bias + G5 + u));
                        float r  = hsig(__ldg(xp + U_ + u) + ar +
                                        __ldg(bias + G5 + U_ + u));
                        float hh = tanhf(__ldg(xp + 2 * U_ + u) +
                                         r * (ah + __ldg(bias + G5 + 2 * U_ + u)));
                        float hold = __ldcg(g_h + (long)b * U_ + u);
                        float h1 = z * hold + (1.0f - z) * hh;
                        __stcg(g_h1a + (long)b * U_ + u, h1);
                        h1r[i][p][h2] = h1;
                        hlr[i][p][h2] = al + __ldg(bias + G5 + 3 * U_ + u);
                    }
                }
            }
        }
        stageB_chunk<3>(Wt, G3, u0, 0, Bs);
        grid_bar(++barno * NBLK);

        // ---- phase T0 ----
        mm_tile_db<3>(As, Bs, g_h1a, Wt, G3, m0, u0, acc);
        k_reduce<3>(Red, acc);
        if (tid < 128) {
#pragma unroll
            for (int i = 0; i < 2; i++) {
                const int b = mBase + i;
#pragma unroll
                for (int p = 0; p < 2; p++) {
                    float2 vz = up(acc[0 + i * 2 + p]);
                    float2 vr = up(acc[4 + i * 2 + p]);
                    float2 vh = up(acc[8 + i * 2 + p]);
#pragma unroll
                    for (int h2 = 0; h2 < 2; h2++) {
                        const int u = uBase + p * 2 + h2;
                        float az = h2 ? vz.y : vz.x;
                        float ar = h2 ? vr.y : vr.x;
                        float ah = h2 ? vh.y : vh.x;
                        float zt = hsig(az + __ldg(tbias + u));
                        float rt = hsig(ar + __ldg(tbias + U_ + u));
                        float ht = tanhf(rt * (ah + __ldg(tbias + 2 * U_ + u)));
                        float h1 = zt * h1r[i][p][h2] + (1.0f - zt) * ht;
                        __stcg(g_h1b + (long)b * U_ + u, h1);
                        h1r[i][p][h2] = h1;
                    }
                }
            }
        }
        stageB_chunk<3>(Wt1, G3, u0, 0, Bs);
        grid_bar(++barno * NBLK);

        // ---- phase T1 + final combine ----
        mm_tile_db<3>(As, Bs, g_h1b, Wt1, G3, m0, u0, acc);
        k_reduce<3>(Red, acc);
        if (tid < 128) {
#pragma unroll
            for (int i = 0; i < 2; i++) {
                const int b = mBase + i;
                const float* xp = g_xg + ((long)b * T_ + t) * G5;
#pragma unroll
                for (int p = 0; p < 2; p++) {
                    float2 vz = up(acc[0 + i * 2 + p]);
                    float2 vr = up(acc[4 + i * 2 + p]);
                    float2 vh = up(acc[8 + i * 2 + p]);
#pragma unroll
                    for (int h2 = 0; h2 < 2; h2++) {
                        const int u = uBase + p * 2 + h2;
                        float az = h2 ? vz.y : vz.x;
                        float ar = h2 ? vr.y : vr.x;
                        float ah = h2 ? vh.y : vh.x;
                        float zt = hsig(az + __ldg(tbias + G3 + u));
                        float rt = hsig(ar + __ldg(tbias + G3 + U_ + u));
                        float ht = tanhf(rt * (ah + __ldg(tbias + G3 + 2 * U_ + u)));
                        float h1 = zt * h1r[i][p][h2] + (1.0f - zt) * ht;
                        float l  = hsig(__ldg(xp + 3 * U_ + u) + hlr[i][p][h2]);
                        float ho = l * h1 +
                                   (1.0f - l) * tanhf(__ldg(xp + 4 * U_ + u));
                        __stcg(g_h + (long)b * U_ + u, ho);
                        out[((long)b * T_ + t) * U_ + u] = ho;
                    }
                }
            }
        }
        stageB_chunk<4>(Wr, G4, u0, 0, Bs);
        grid_bar(++barno * NBLK);
    }
}

// ---------------------------------------------------------------------------
extern "C" void kernel_launch(void* const* d_in, const int* in_sizes, int n_in,
                              void* d_out, int out_size) {
    (void)in_sizes; (void)n_in; (void)out_size;
    const float* x      = (const float*)d_in[0];
    const float* h0     = (const float*)d_in[1];
    const float* kernel = (const float*)d_in[2];
    const float* Wr     = (const float*)d_in[3];
    const float* Wt     = (const float*)d_in[4];
    const float* bias   = (const float*)d_in[5];
    const float* tbias  = (const float*)d_in[6];
    float* out = (float*)d_out;

    static int smem_set = 0;
    if (!smem_set) {
        cudaFuncSetAttribute(scan_kernel,
                             cudaFuncAttributeMaxDynamicSharedMemorySize,
                             SMEM_BYTES);
        smem_set = 1;
    }

    init_h_kernel<<<(B_ * U_ + 255) / 256, 256>>>(h0);
    xg_gemm_kernel<<<dim3(G5 / 128, (B_ * T_) / 128), 256>>>(x, kernel, bias);
    scan_kernel<<<NBLK, NTHR, SMEM_BYTES>>>(Wr, Wt, bias, tbias, out);
}